// round 10
// baseline (speedup 1.0000x reference)
#include <cuda_runtime.h>
#include <cuda_fp16.h>

// EgoAttentionNetwork: B=8192, E=64, F_IN=7, D=64, H=4, HD=16
// Round-9: TWO batches per CTA. Each warp's k-loop loads packed fp16 weights
// once and applies them to both batches' activations (register amortization).
// hT and V^T live in fp16 smem (aT stays fp32). 3 CTAs/SM (63KB smem).

typedef unsigned long long u64;

#define NTHR 256
#define FULLMASK 0xffffffffu
#define CST 68    // column stride (entities) for hTh/aT

__device__ __half  dW0h[448];    // oth_w0 [f][d]
__device__ u64     dW1p[1024];   // oth_w1 packed [kp][lane]: k0(d0,d0+1) k1(d0,d0+1)
__device__ uint4   dKVp[1024];   // [kp][lane]: Wk(k0) Wv(k0) Wk(k1) Wv(k1)
__device__ __half2 dW1ep[2048];  // ego_w1 [kp*64+d] = (W[2kp][d], W[2kp+1][d])
__device__ __half2 dWqp[2048];   // Wq same packing
__device__ __half2 dWcp[2048];   // Wc same packing

static __device__ __forceinline__ u64 fma2(u64 a, u64 b, u64 c) {
    u64 d;
    asm("fma.rn.f32x2 %0, %1, %2, %3;" : "=l"(d) : "l"(a), "l"(b), "l"(c));
    return d;
}
static __device__ __forceinline__ u64 dup2(float x) {
    u64 r;
    asm("mov.b64 %0, {%1, %1};" : "=l"(r) : "f"(x));
    return r;
}
static __device__ __forceinline__ u64 pack2(float a, float b) {
    u64 r;
    asm("mov.b64 %0, {%1, %2};" : "=l"(r) : "f"(a), "f"(b));
    return r;
}
static __device__ __forceinline__ float2 unpack2(u64 v) {
    float2 r;
    asm("mov.b64 {%0, %1}, %2;" : "=f"(r.x), "=f"(r.y) : "l"(v));
    return r;
}
static __device__ __forceinline__ float2 h2f(unsigned int u) {
    __half2 h = *reinterpret_cast<__half2*>(&u);
    return __half22float2(h);
}
static __device__ __forceinline__ unsigned int f2h2(float a, float b) {
    __half2 h = __floats2half2_rn(a, b);
    return *reinterpret_cast<unsigned int*>(&h);
}
// load 4 fp16 entities (broadcast) -> two f32x2 operands
static __device__ __forceinline__ void loadAh(const __half* p, u64& a, u64& b) {
    uint2 v = *reinterpret_cast<const uint2*>(p);
    float2 f0 = h2f(v.x), f1 = h2f(v.y);
    a = pack2(f0.x, f0.y);
    b = pack2(f1.x, f1.y);
}
// load 4 fp32 entities (broadcast) -> two f32x2 operands
static __device__ __forceinline__ void loadAf(const float* p, u64& a, u64& b) {
    float4 v = *reinterpret_cast<const float4*>(p);
    a = pack2(v.x, v.y);
    b = pack2(v.z, v.w);
}

__global__ void prep_weights(const float* __restrict__ oth_w0,
                             const float* __restrict__ oth_w1,
                             const float* __restrict__ Wk,
                             const float* __restrict__ Wv,
                             const float* __restrict__ ego_w1,
                             const float* __restrict__ Wq,
                             const float* __restrict__ Wc)
{
    const int i = blockIdx.x * 256 + threadIdx.x;   // 0..2047
    if (i < 448) dW0h[i] = __float2half(__ldg(oth_w0 + i));
    if (i < 1024) {
        const int kp = i >> 5, dt2 = i & 31, d0 = dt2 * 2;
        const int k0 = 2 * kp * 64 + d0, k1 = (2 * kp + 1) * 64 + d0;
        unsigned lo = f2h2(__ldg(oth_w1 + k0), __ldg(oth_w1 + k0 + 1));
        unsigned hi = f2h2(__ldg(oth_w1 + k1), __ldg(oth_w1 + k1 + 1));
        dW1p[i] = (u64)lo | ((u64)hi << 32);
        uint4 kv;
        kv.x = f2h2(__ldg(Wk + k0), __ldg(Wk + k0 + 1));
        kv.y = f2h2(__ldg(Wv + k0), __ldg(Wv + k0 + 1));
        kv.z = f2h2(__ldg(Wk + k1), __ldg(Wk + k1 + 1));
        kv.w = f2h2(__ldg(Wv + k1), __ldg(Wv + k1 + 1));
        dKVp[i] = kv;
    }
    {
        const int kp = i >> 6, d = i & 63;
        const int k0 = 2 * kp * 64 + d, k1 = (2 * kp + 1) * 64 + d;
        dW1ep[i] = __floats2half2_rn(__ldg(ego_w1 + k0), __ldg(ego_w1 + k1));
        dWqp[i]  = __floats2half2_rn(__ldg(Wq + k0),     __ldg(Wq + k1));
        dWcp[i]  = __floats2half2_rn(__ldg(Wc + k0),     __ldg(Wc + k1));
    }
}

struct __align__(16) SmemB {
    float  aT[64 * CST];   // fp32 input_all^T           17408 B
    __half hTh[64 * CST];  // fp16 hidden^T / V^T overlay 8704 B
    float  sX[64 * 8];     //                              2048 B
    float  h0[64];
    float  sEgo[64];
    float  sQ[64];
    float  sO[64];
    float  sS[256];
    float  sP[256];
    int    sIdx[64];
    int    nOth, uniformF, egoAct, pad0;
};

__global__ void __launch_bounds__(NTHR, 3)
ego_attn_kernel(const float* __restrict__ x,
                const float* __restrict__ ego_w0, const float* __restrict__ ego_b0,
                const float* __restrict__ ego_b1,
                const float* __restrict__ oth_b0, const float* __restrict__ oth_b1,
                float* __restrict__ out)
{
    extern __shared__ char smem_raw[];
    SmemB* sb = reinterpret_cast<SmemB*>(smem_raw);
    const int tid = threadIdx.x;
    const int lane = tid & 31;
    const int w = tid >> 5;
    const int d0 = lane * 2;                    // feature pair per lane
    const int etr = (w + (blockIdx.x & 7)) & 7; // rotated entity tile
    const long bBase = (long)blockIdx.x * 2;
    const __half2* W0h2 = reinterpret_cast<const __half2*>(dW0h);

    // ---- PH1: load x for both batches; init scores ----
    for (int idx = tid; idx < 896; idx += NTHR) {
        int bb = idx >= 448;
        int j = idx - bb * 448;
        int e = j / 7, f = j - e * 7;
        sb[bb].sX[e * 8 + f] = __ldg(x + (bBase + bb) * 448 + j);
    }
    sb[0].sS[tid] = -1e30f;
    sb[1].sS[tid] = -1e30f;
    __syncthreads();

    // ---- PH2: warps 0-1 compaction (b0,b1) | warps 2-3 ego layer0 ----
    if (w < 2) {
        SmemB& s = sb[w];
        int egoA = (s.sX[0] >= 0.5f) ? 1 : 0;
        unsigned m1 = __ballot_sync(FULLMASK, (lane >= 1) && (s.sX[lane * 8] >= 0.5f));
        unsigned m2 = __ballot_sync(FULLMASK, s.sX[(lane + 32) * 8] >= 0.5f);
        int cnt = __popc(m1) + __popc(m2);
        unsigned lmask = (1u << lane) - 1u;
        if (cnt == 0 && !egoA) {
            s.sIdx[lane] = lane + 1;
            if (lane < 31) s.sIdx[lane + 32] = lane + 33;
            if (lane == 0) { s.nOth = 63; s.uniformF = 1; s.egoAct = egoA; }
        } else {
            if ((lane >= 1) && (m1 >> lane & 1u))
                s.sIdx[__popc(m1 & lmask)] = lane;
            if (m2 >> lane & 1u)
                s.sIdx[__popc(m1) + __popc(m2 & lmask)] = lane + 32;
            if (lane == 0) { s.nOth = cnt; s.uniformF = 0; s.egoAct = egoA; }
        }
    } else if (w < 4) {
        SmemB& s = sb[w - 2];
        #pragma unroll
        for (int r = 0; r < 2; r++) {
            int d = lane + r * 32;
            float acc = __ldg(ego_b0 + d);
            #pragma unroll
            for (int f = 0; f < 7; f++)
                acc += s.sX[f] * __ldg(ego_w0 + f * 64 + d);
            s.h0[d] = fmaxf(acc, 0.f);
        }
    }
    __syncthreads();

    int nOthA[2], uniA[2], egoAA[2], padA[2], cEgoA[2];
    #pragma unroll
    for (int i = 0; i < 2; i++) {
        nOthA[i] = sb[i].nOth;
        uniA[i] = sb[i].uniformF;
        egoAA[i] = sb[i].egoAct;
        cEgoA[i] = nOthA[i];
        int pm = (nOthA[i] + 1 + 3) & ~3; if (pm > 64) pm = 64;
        padA[i] = pm;
    }
    const int npmax = ((padA[0] > padA[1] ? padA[0] : padA[1]) + 31) >> 5;

    // ---- PH3: others layer0 (96 thr/batch) | ego layer1 (32 thr/batch) ----
    if (tid < 192) {
        const int bb = tid >= 96;
        SmemB& s = sb[bb];
        const int t96 = tid - bb * 96;
        const int nO = nOthA[bb];
        for (int idx = t96; idx < nO * 32; idx += 96) {
            int i = idx >> 5, dd = (idx & 31) * 2;
            int e = s.sIdx[i];
            const float* xr = s.sX + e * 8;
            float2 bb2 = *reinterpret_cast<const float2*>(oth_b0 + dd);
            float ax = bb2.x, ay = bb2.y;
            #pragma unroll
            for (int f = 0; f < 7; f++) {
                float2 wv = __half22float2(W0h2[f * 32 + (dd >> 1)]);
                float xv = xr[f];
                ax += xv * wv.x; ay += xv * wv.y;
            }
            s.hTh[dd * CST + i]       = __float2half(fmaxf(ax, 0.f));
            s.hTh[(dd + 1) * CST + i] = __float2half(fmaxf(ay, 0.f));
        }
        // zero-fill pad columns [nOth, PADMAX)
        const int pm = padA[bb];
        for (int z = t96; z < 256; z += 96) {
            int d = z >> 2, c = nO + (z & 3);
            if (c < pm) s.hTh[d * CST + c] = __float2half(0.f);
        }
    } else {
        const int bb = tid >= 224;
        SmemB& s = sb[bb];
        const int d = tid - 192 - bb * 32;      // 0..31
        float a0 = __ldg(ego_b1 + d),      a1 = 0.f;
        float b0 = __ldg(ego_b1 + d + 32), b1 = 0.f;
        #pragma unroll 8
        for (int kp = 0; kp < 32; kp++) {
            float2 wl = __half22float2(__ldg(&dW1ep[kp * 64 + d]));
            float2 wh = __half22float2(__ldg(&dW1ep[kp * 64 + d + 32]));
            float2 hv = *reinterpret_cast<const float2*>(&s.h0[2 * kp]);
            a0 += hv.x * wl.x;  a1 += hv.y * wl.y;
            b0 += hv.x * wh.x;  b1 += hv.y * wh.y;
        }
        s.sEgo[d]      = fmaxf(a0 + a1, 0.f);
        s.sEgo[d + 32] = fmaxf(b0 + b1, 0.f);
    }
    __syncthreads();

    // ---- PH4: layer1 GEMM hTh->aT, both batches share weight registers ----
    for (int ep = 0; ep < npmax; ep++) {
        const int e0 = ep * 32 + etr * 4;
        const bool a0v = (e0 < padA[0]);
        const bool a1v = (e0 < padA[1]);
        if (!(a0v || a1v)) continue;
        u64 A00 = 0, A01 = 0, A10 = 0, A11 = 0;
        u64 B00 = 0, B01 = 0, B10 = 0, B11 = 0;
        const __half* h0p = sb[0].hTh + e0;
        const __half* h1p = sb[1].hTh + e0;
        #pragma unroll 4
        for (int kp = 0; kp < 32; kp++) {
            u64 wp = __ldg(&dW1p[kp * 32 + lane]);
            float2 wA = h2f((unsigned)wp);
            float2 wB = h2f((unsigned)(wp >> 32));
            u64 wxA = dup2(wA.x), wyA = dup2(wA.y);
            u64 wxB = dup2(wB.x), wyB = dup2(wB.y);
            if (a0v) {
                u64 p01, p23;
                loadAh(h0p + (2 * kp) * CST, p01, p23);
                A00 = fma2(p01, wxA, A00);  A01 = fma2(p23, wxA, A01);
                A10 = fma2(p01, wyA, A10);  A11 = fma2(p23, wyA, A11);
                loadAh(h0p + (2 * kp + 1) * CST, p01, p23);
                A00 = fma2(p01, wxB, A00);  A01 = fma2(p23, wxB, A01);
                A10 = fma2(p01, wyB, A10);  A11 = fma2(p23, wyB, A11);
            }
            if (a1v) {
                u64 p01, p23;
                loadAh(h1p + (2 * kp) * CST, p01, p23);
                B00 = fma2(p01, wxA, B00);  B01 = fma2(p23, wxA, B01);
                B10 = fma2(p01, wyA, B10);  B11 = fma2(p23, wyA, B11);
                loadAh(h1p + (2 * kp + 1) * CST, p01, p23);
                B00 = fma2(p01, wxB, B00);  B01 = fma2(p23, wxB, B01);
                B10 = fma2(p01, wyB, B10);  B11 = fma2(p23, wyB, B11);
            }
        }
        const float b0v = __ldg(oth_b1 + d0);
        const float b1v = __ldg(oth_b1 + d0 + 1);
        #pragma unroll
        for (int i = 0; i < 2; i++) {
            if (!(i == 0 ? a0v : a1v)) continue;
            SmemB& s = sb[i];
            float2 c0 = unpack2(i == 0 ? A00 : B00);
            float2 c1 = unpack2(i == 0 ? A01 : B01);
            float2 c2 = unpack2(i == 0 ? A10 : B10);
            float2 c3 = unpack2(i == 0 ? A11 : B11);
            float r0[4] = { fmaxf(c0.x + b0v, 0.f), fmaxf(c0.y + b0v, 0.f),
                            fmaxf(c1.x + b0v, 0.f), fmaxf(c1.y + b0v, 0.f) };
            float r1[4] = { fmaxf(c2.x + b1v, 0.f), fmaxf(c2.y + b1v, 0.f),
                            fmaxf(c3.x + b1v, 0.f), fmaxf(c3.y + b1v, 0.f) };
            const int patch = cEgoA[i] - e0;
            if (patch >= 0 && patch < 4) {
                r0[patch] = s.sEgo[d0];
                r1[patch] = s.sEgo[d0 + 1];
            }
            *reinterpret_cast<float4*>(s.aT + d0 * CST + e0) =
                make_float4(r0[0], r0[1], r0[2], r0[3]);
            *reinterpret_cast<float4*>(s.aT + (d0 + 1) * CST + e0) =
                make_float4(r1[0], r1[1], r1[2], r1[3]);
        }
    }
    __syncthreads();

    // ---- PH4b: q = Wq^T sEgo (threads 0-127, 64 per batch) ----
    if (tid < 128) {
        const int bb = tid >> 6, d = tid & 63;
        SmemB& s = sb[bb];
        float a0 = 0.f, a1 = 0.f;
        #pragma unroll 8
        for (int kp = 0; kp < 32; kp++) {
            float2 wv = __half22float2(__ldg(&dWqp[kp * 64 + d]));
            float2 ev = *reinterpret_cast<const float2*>(&s.sEgo[2 * kp]);
            a0 += ev.x * wv.x;
            a1 += ev.y * wv.y;
        }
        s.sQ[d] = a0 + a1;
    }
    __syncthreads();

    // ---- PH5: fused K+V GEMM, both batches share weight registers ----
    for (int ep = 0; ep < npmax; ep++) {
        const int e0 = ep * 32 + etr * 4;
        const bool a0v = (e0 < padA[0]);
        const bool a1v = (e0 < padA[1]);
        if (!(a0v || a1v)) continue;
        u64 K0[4] = {0, 0, 0, 0}, V0[4] = {0, 0, 0, 0};
        u64 K1[4] = {0, 0, 0, 0}, V1[4] = {0, 0, 0, 0};
        const float* a0p = sb[0].aT + e0;
        const float* a1p = sb[1].aT + e0;
        #pragma unroll 2
        for (int kp = 0; kp < 32; kp++) {
            uint4 kv = __ldg(&dKVp[kp * 32 + lane]);
            float2 wk0 = h2f(kv.x), wv0 = h2f(kv.y);
            float2 wk1 = h2f(kv.z), wv1 = h2f(kv.w);
            u64 kx0 = dup2(wk0.x), ky0 = dup2(wk0.y);
            u64 vx0 = dup2(wv0.x), vy0 = dup2(wv0.y);
            u64 kx1 = dup2(wk1.x), ky1 = dup2(wk1.y);
            u64 vx1 = dup2(wv1.x), vy1 = dup2(wv1.y);
            if (a0v) {
                u64 p01, p23;
                loadAf(a0p + (2 * kp) * CST, p01, p23);
                K0[0] = fma2(p01, kx0, K0[0]);  K0[1] = fma2(p23, kx0, K0[1]);
                K0[2] = fma2(p01, ky0, K0[2]);  K0[3] = fma2(p23, ky0, K0[3]);
                V0[0] = fma2(p01, vx0, V0[0]);  V0[1] = fma2(p23, vx0, V0[1]);
                V0[2] = fma2(p01, vy0, V0[2]);  V0[3] = fma2(p23, vy0, V0[3]);
                loadAf(a0p + (2 * kp + 1) * CST, p01, p23);
                K0[0] = fma2(p01, kx1, K0[0]);  K0[1] = fma2(p23, kx1, K0[1]);
                K0[2] = fma2(p01, ky1, K0[2]);  K0[3] = fma2(p23, ky1, K0[3]);
                V0[0] = fma2(p01, vx1, V0[0]);  V0[1] = fma2(p23, vx1, V0[1]);
                V0[2] = fma2(p01, vy1, V0[2]);  V0[3] = fma2(p23, vy1, V0[3]);
            }
            if (a1v) {
                u64 p01, p23;
                loadAf(a1p + (2 * kp) * CST, p01, p23);
                K1[0] = fma2(p01, kx0, K1[0]);  K1[1] = fma2(p23, kx0, K1[1]);
                K1[2] = fma2(p01, ky0, K1[2]);  K1[3] = fma2(p23, ky0, K1[3]);
                V1[0] = fma2(p01, vx0, V1[0]);  V1[1] = fma2(p23, vx0, V1[1]);
                V1[2] = fma2(p01, vy0, V1[2]);  V1[3] = fma2(p23, vy0, V1[3]);
                loadAf(a1p + (2 * kp + 1) * CST, p01, p23);
                K1[0] = fma2(p01, kx1, K1[0]);  K1[1] = fma2(p23, kx1, K1[1]);
                K1[2] = fma2(p01, ky1, K1[2]);  K1[3] = fma2(p23, ky1, K1[3]);
                V1[0] = fma2(p01, vx1, V1[0]);  V1[1] = fma2(p23, vx1, V1[1]);
                V1[2] = fma2(p01, vy1, V1[2]);  V1[3] = fma2(p23, vy1, V1[3]);
            }
        }
        #pragma unroll
        for (int i = 0; i < 2; i++) {
            if (!(i == 0 ? a0v : a1v)) continue;
            SmemB& s = sb[i];
            u64* Kp = (i == 0) ? K0 : K1;
            u64* Vp = (i == 0) ? V0 : V1;
            u64 q0 = dup2(s.sQ[d0]), q1 = dup2(s.sQ[d0 + 1]);
            u64 s01 = fma2(Kp[0], q0, (u64)0), s23 = fma2(Kp[1], q0, (u64)0);
            s01 = fma2(Kp[2], q1, s01);        s23 = fma2(Kp[3], q1, s23);
            float2 f01 = unpack2(s01), f23 = unpack2(s23);
            float sc0 = f01.x, sc1 = f01.y, sc2 = f23.x, sc3 = f23.y;
            #pragma unroll
            for (int o = 1; o < 8; o <<= 1) {
                sc0 += __shfl_xor_sync(FULLMASK, sc0, o);
                sc1 += __shfl_xor_sync(FULLMASK, sc1, o);
                sc2 += __shfl_xor_sync(FULLMASK, sc2, o);
                sc3 += __shfl_xor_sync(FULLMASK, sc3, o);
            }
            if ((lane & 7) == 0) {
                const int h = lane >> 3;
                float scv[4] = {sc0, sc1, sc2, sc3};
                #pragma unroll
                for (int m = 0; m < 4; m++) {
                    int col = e0 + m;
                    bool act = uniA[i] ? (col < nOthA[i] + 1)
                                       : ((col < nOthA[i]) ||
                                          (col == cEgoA[i] && egoAA[i]));
                    s.sS[h * 64 + col] = act ? scv[m] * 0.25f : -1e30f;
                }
            }
            // V^T -> hTh overlay (fp16)
            float2 va = unpack2(Vp[0]), vb = unpack2(Vp[1]);   // feature d0
            float2 vc = unpack2(Vp[2]), vd = unpack2(Vp[3]);   // feature d0+1
            uint2 r0 = make_uint2(f2h2(va.x, va.y), f2h2(vb.x, vb.y));
            uint2 r1 = make_uint2(f2h2(vc.x, vc.y), f2h2(vd.x, vd.y));
            *reinterpret_cast<uint2*>(s.hTh + d0 * CST + e0)       = r0;
            *reinterpret_cast<uint2*>(s.hTh + (d0 + 1) * CST + e0) = r1;
        }
    }
    __syncthreads();

    // ---- PH6: softmax (warps 0-3 -> b0 heads, warps 4-7 -> b1 heads) ----
    {
        const int bb = w >> 2, h = w & 3;
        SmemB& s = sb[bb];
        if (uniA[bb]) {
            const float p = 1.0f / 64.0f;
            s.sP[h * 64 + lane] = p;
            s.sP[h * 64 + lane + 32] = p;
        } else {
            float s0 = s.sS[h * 64 + lane];
            float s1 = s.sS[h * 64 + lane + 32];
            float m = fmaxf(s0, s1);
            #pragma unroll
            for (int off = 16; off; off >>= 1)
                m = fmaxf(m, __shfl_xor_sync(FULLMASK, m, off));
            float e0v = __expf(s0 - m);
            float e1v = __expf(s1 - m);
            float sum = e0v + e1v;
            #pragma unroll
            for (int off = 16; off; off >>= 1)
                sum += __shfl_xor_sync(FULLMASK, sum, off);
            float inv = 1.0f / sum;
            s.sP[h * 64 + lane] = e0v * inv;
            s.sP[h * 64 + lane + 32] = e1v * inv;
        }
    }
    __syncthreads();

    // ---- PH7: attention-weighted sum from fp16 V^T (threads 0-127) ----
    if (tid < 128) {
        const int bb = tid >> 6, d = tid & 63, h = d >> 4;
        SmemB& s = sb[bb];
        const float* pr = s.sP + h * 64;
        const __half* vr = s.hTh + d * CST;
        float a0 = 0.f, a1 = 0.f;
        const int pm = padA[bb];
        for (int i = 0; i < pm; i += 2) {
            float2 v = h2f(*reinterpret_cast<const unsigned int*>(vr + i));
            a0 += pr[i] * v.x;
            a1 += pr[i + 1] * v.y;
        }
        s.sO[d] = a0 + a1;
    }
    __syncthreads();

    // ---- PH8: epilogue (threads 0-127) ----
    if (tid < 128) {
        const int bb = tid >> 6, d = tid & 63;
        SmemB& s = sb[bb];
        float a0 = 0.f, a1 = 0.f;
        #pragma unroll 8
        for (int kp = 0; kp < 32; kp++) {
            float2 wv = __half22float2(__ldg(&dWcp[kp * 64 + d]));
            float2 ov = *reinterpret_cast<const float2*>(&s.sO[2 * kp]);
            a0 += ov.x * wv.x;
            a1 += ov.y * wv.y;
        }
        out[(bBase + bb) * 64 + d] = ((a0 + a1) + s.sEgo[d]) * 0.5f;
    }
}

extern "C" void kernel_launch(void* const* d_in, const int* in_sizes, int n_in,
                              void* d_out, int out_size) {
    (void)in_sizes; (void)n_in; (void)out_size;
    const float* x      = (const float*)d_in[0];
    const float* ego_w0 = (const float*)d_in[1];
    const float* ego_b0 = (const float*)d_in[2];
    const float* ego_w1 = (const float*)d_in[3];
    const float* ego_b1 = (const float*)d_in[4];
    const float* oth_w0 = (const float*)d_in[5];
    const float* oth_b0 = (const float*)d_in[6];
    const float* oth_w1 = (const float*)d_in[7];
    const float* oth_b1 = (const float*)d_in[8];
    const float* Wk     = (const float*)d_in[9];
    const float* Wv     = (const float*)d_in[10];
    const float* Wq     = (const float*)d_in[11];
    const float* Wc     = (const float*)d_in[12];
    float* out = (float*)d_out;

    const int smem = 2 * (int)sizeof(SmemB);
    cudaFuncSetAttribute(ego_attn_kernel,
                         cudaFuncAttributeMaxDynamicSharedMemorySize, smem);
    prep_weights<<<8, 256>>>(oth_w0, oth_w1, Wk, Wv, ego_w1, Wq, Wc);
    ego_attn_kernel<<<4096, NTHR, smem>>>(x, ego_w0, ego_b0, ego_b1,
                                          oth_b0, oth_b1, out);
}

// round 11
// speedup vs baseline: 2.4778x; 2.4778x over previous
#include <cuda_runtime.h>
#include <cuda_fp16.h>

// EgoAttentionNetwork: B=8192, E=64, F_IN=7, D=64, H=4, HD=16
// Round-10: tensor-core path. The three 64-wide GEMMs (others layer1, K, V)
// run as fp16 mma.sync.m16n8k16 with fp32 accumulators. Weights pre-packed
// into B-fragment layout by the prep kernel; activations fp16 in smem
// (entity-major, stride 72 halves) loaded via ldmatrix. K scores reduced
// in-fragment; V fragments held in registers across softmax.

typedef unsigned int u32;

#define NTHR 256
#define AROW 72
#define FULLMASK 0xffffffffu

__device__ __half  dW0h[448];    // oth_w0 [f][d] fp16
__device__ uint2   dF1[1024];    // oth_w1 B-fragments [kt(4)][nt(8)][lane(32)]
__device__ uint2   dFk[1024];    // Wk fragments
__device__ uint2   dFv[1024];    // Wv fragments
__device__ __half2 dW1ep[2048];  // ego_w1 k-pair packed
__device__ __half2 dWqp[2048];   // Wq k-pair packed
__device__ __half2 dWcp[2048];   // Wc k-pair packed

static __device__ __forceinline__ unsigned int f2h2(float a, float b) {
    __half2 h = __floats2half2_rn(a, b);
    return *reinterpret_cast<unsigned int*>(&h);
}
static __device__ __forceinline__ float2 h2f(unsigned int u) {
    __half2 h = *reinterpret_cast<__half2*>(&u);
    return __half22float2(h);
}
static __device__ __forceinline__ u32 s2u(const void* p) {
    return (u32)__cvta_generic_to_shared(p);
}
static __device__ __forceinline__ void ldsm4(u32* a, u32 addr) {
    asm volatile("ldmatrix.sync.aligned.m8n8.x4.shared.b16 {%0,%1,%2,%3}, [%4];"
                 : "=r"(a[0]), "=r"(a[1]), "=r"(a[2]), "=r"(a[3]) : "r"(addr));
}
static __device__ __forceinline__ void mma16816(
    float& c0, float& c1, float& c2, float& c3,
    const u32* a, u32 b0, u32 b1)
{
    asm volatile(
        "mma.sync.aligned.m16n8k16.row.col.f32.f16.f16.f32 "
        "{%0,%1,%2,%3}, {%4,%5,%6,%7}, {%8,%9}, {%0,%1,%2,%3};"
        : "+f"(c0), "+f"(c1), "+f"(c2), "+f"(c3)
        : "r"(a[0]), "r"(a[1]), "r"(a[2]), "r"(a[3]), "r"(b0), "r"(b1));
}

__device__ __forceinline__ u32 pkw(const float* W, int k, int n) {
    return f2h2(__ldg(W + k * 64 + n), __ldg(W + (k + 1) * 64 + n));
}

__global__ void prep_weights(const float* __restrict__ oth_w0,
                             const float* __restrict__ oth_w1,
                             const float* __restrict__ Wk,
                             const float* __restrict__ Wv,
                             const float* __restrict__ ego_w1,
                             const float* __restrict__ Wq,
                             const float* __restrict__ Wc)
{
    const int i = blockIdx.x * 256 + threadIdx.x;   // 0..2047
    if (i < 448) dW0h[i] = __float2half(__ldg(oth_w0 + i));
    if (i < 1024) {
        // fragment index: i = (kt*8 + nt)*32 + lane
        const int lane = i & 31, nt = (i >> 5) & 7, kt = i >> 8;
        const int n = nt * 8 + (lane >> 2);
        const int k = kt * 16 + (lane & 3) * 2;
        dF1[i] = make_uint2(pkw(oth_w1, k, n), pkw(oth_w1, k + 8, n));
        dFk[i] = make_uint2(pkw(Wk, k, n),     pkw(Wk, k + 8, n));
        dFv[i] = make_uint2(pkw(Wv, k, n),     pkw(Wv, k + 8, n));
    }
    {
        const int kp = i >> 6, d = i & 63;
        const int k0 = 2 * kp * 64 + d, k1 = (2 * kp + 1) * 64 + d;
        dW1ep[i] = __floats2half2_rn(__ldg(ego_w1 + k0), __ldg(ego_w1 + k1));
        dWqp[i]  = __floats2half2_rn(__ldg(Wq + k0),     __ldg(Wq + k1));
        dWcp[i]  = __floats2half2_rn(__ldg(Wc + k0),     __ldg(Wc + k1));
    }
}

struct __align__(16) SmemT {
    __half Ah0[64 * AROW];   // hidden (layer0 out), entity-major fp16
    __half Ah1[64 * AROW];   // input_all (layer1 out), entity-major fp16
    float  sX[64 * 8];
    float  h0[64];
    float  sEgo[64];
    float  sQ[64];
    float  sO[64];
    float  sS[256];
    float  sP[256];
    int    sIdx[64];
    int    nOth, uniformF, egoAct;
};

__device__ __forceinline__ void softmax_phase(SmemT& s, int uniformF, int tid) {
    if (tid < 128) {
        const int h = tid >> 5, ln = tid & 31;
        if (uniformF) {
            const float p = 1.0f / 64.0f;
            s.sP[h * 64 + ln] = p;
            s.sP[h * 64 + ln + 32] = p;
        } else {
            float s0 = s.sS[h * 64 + ln];
            float s1 = s.sS[h * 64 + ln + 32];
            float m = fmaxf(s0, s1);
            #pragma unroll
            for (int off = 16; off; off >>= 1)
                m = fmaxf(m, __shfl_xor_sync(FULLMASK, m, off));
            float e0 = __expf(s0 - m);
            float e1 = __expf(s1 - m);
            float sum = e0 + e1;
            #pragma unroll
            for (int off = 16; off; off >>= 1)
                sum += __shfl_xor_sync(FULLMASK, sum, off);
            float inv = 1.0f / sum;
            s.sP[h * 64 + ln] = e0 * inv;
            s.sP[h * 64 + ln + 32] = e1 * inv;
        }
    }
}

__global__ void __launch_bounds__(NTHR, 4)
ego_attn_kernel(const float* __restrict__ x,
                const float* __restrict__ ego_w0, const float* __restrict__ ego_b0,
                const float* __restrict__ ego_b1,
                const float* __restrict__ oth_b0, const float* __restrict__ oth_b1,
                float* __restrict__ out)
{
    __shared__ SmemT s;
    const int tid = threadIdx.x;
    const int lane = tid & 31;
    const int w = tid >> 5;
    const int mt = w & 1;        // m16 tile within a 32-row pass
    const int g = w >> 1;        // head (= pair of n8 tiles)
    const long b = blockIdx.x;
    const float* xb = x + b * 448;
    const __half2* W0h2 = reinterpret_cast<const __half2*>(dW0h);

    // ---- PH1: load x; init score/out buffers ----
    for (int idx = tid; idx < 448; idx += NTHR) {
        int e = idx / 7, f = idx - (idx / 7) * 7;
        s.sX[e * 8 + f] = __ldg(xb + idx);
    }
    s.sS[tid] = -1e30f;
    if (tid < 64) s.sO[tid] = 0.f;
    __syncthreads();

    // ---- PH2: compaction (warp0) | ego layer0 (warp1) ----
    if (tid < 32) {
        int egoA = (s.sX[0] >= 0.5f) ? 1 : 0;
        unsigned m1 = __ballot_sync(FULLMASK, (lane >= 1) && (s.sX[lane * 8] >= 0.5f));
        unsigned m2 = __ballot_sync(FULLMASK, s.sX[(lane + 32) * 8] >= 0.5f);
        int cnt = __popc(m1) + __popc(m2);
        unsigned lmask = (1u << lane) - 1u;
        if (cnt == 0 && !egoA) {
            s.sIdx[lane] = lane + 1;
            if (lane < 31) s.sIdx[lane + 32] = lane + 33;
            if (lane == 0) { s.nOth = 63; s.uniformF = 1; s.egoAct = egoA; }
        } else {
            if ((lane >= 1) && (m1 >> lane & 1u))
                s.sIdx[__popc(m1 & lmask)] = lane;
            if (m2 >> lane & 1u)
                s.sIdx[__popc(m1) + __popc(m2 & lmask)] = lane + 32;
            if (lane == 0) { s.nOth = cnt; s.uniformF = 0; s.egoAct = egoA; }
        }
    } else if (tid < 64) {
        const int ln = tid - 32;
        #pragma unroll
        for (int r = 0; r < 2; r++) {
            int d = ln + r * 32;
            float acc = __ldg(ego_b0 + d);
            #pragma unroll
            for (int f = 0; f < 7; f++)
                acc += s.sX[f] * __ldg(ego_w0 + f * 64 + d);
            s.h0[d] = fmaxf(acc, 0.f);
        }
    }
    __syncthreads();

    const int nOth = s.nOth;
    const int uniformF = s.uniformF;
    const int egoAct = s.egoAct;
    const int cEgo = nOth;
    const int nTot = nOth + 1;
    const int Mpad = (nTot <= 32) ? 32 : 64;
    const int npass = Mpad >> 5;

    // ---- PH3: others layer0 -> Ah0 (192 thr) | ego layer1 (64 thr) ----
    if (tid < 192) {
        for (int idx = tid; idx < nOth * 32; idx += 192) {
            int i = idx >> 5, dd = (idx & 31) * 2;
            int e = s.sIdx[i];
            const float* xr = s.sX + e * 8;
            float2 bb = *reinterpret_cast<const float2*>(oth_b0 + dd);
            float ax = bb.x, ay = bb.y;
            #pragma unroll
            for (int f = 0; f < 7; f++) {
                float2 wv = __half22float2(W0h2[f * 32 + (dd >> 1)]);
                float xv = xr[f];
                ax += xv * wv.x; ay += xv * wv.y;
            }
            *reinterpret_cast<__half2*>(&s.Ah0[i * AROW + dd]) =
                __floats2half2_rn(fmaxf(ax, 0.f), fmaxf(ay, 0.f));
        }
        // zero-fill pad rows [nOth, Mpad)
        const __half2 z2 = __floats2half2_rn(0.f, 0.f);
        for (int z = tid; z < (Mpad - nOth) * 32; z += 192) {
            int rr = nOth + (z >> 5), dd = (z & 31) * 2;
            *reinterpret_cast<__half2*>(&s.Ah0[rr * AROW + dd]) = z2;
        }
    } else {
        const int d = tid - 192;
        float a0 = __ldg(ego_b1 + d), a1 = 0.f;
        #pragma unroll 8
        for (int kp = 0; kp < 32; kp++) {
            float2 wv = __half22float2(__ldg(&dW1ep[kp * 64 + d]));
            float2 hv = *reinterpret_cast<const float2*>(&s.h0[2 * kp]);
            a0 += hv.x * wv.x;
            a1 += hv.y * wv.y;
        }
        s.sEgo[d] = fmaxf(a0 + a1, 0.f);
    }
    __syncthreads();

    // ---- PH4: layer1 GEMM (HMMA): Ah0 -> Ah1, bias+relu+ego patch ----
    const int col0 = (lane & 3) * 2;  // column offset within an n8 tile
    for (int mp = 0; mp < npass; mp++) {
        const int m_base = mp * 32 + mt * 16;
        u32 A[4][4];
        u32 ab = s2u(s.Ah0 + (m_base + (lane & 15)) * AROW + ((lane >> 4) << 3));
        #pragma unroll
        for (int kt = 0; kt < 4; kt++) ldsm4(A[kt], ab + kt * 32);
        const int r0 = m_base + (lane >> 2), r1 = r0 + 8;
        #pragma unroll
        for (int nt2 = 0; nt2 < 2; nt2++) {
            const int nt = g * 2 + nt2;
            const int cA = nt * 8 + col0;
            float c0 = __ldg(oth_b1 + cA), c1 = __ldg(oth_b1 + cA + 1);
            float c2 = c0, c3 = c1;
            #pragma unroll
            for (int kt = 0; kt < 4; kt++) {
                uint2 bf = __ldg(&dF1[(kt * 8 + nt) * 32 + lane]);
                mma16816(c0, c1, c2, c3, A[kt], bf.x, bf.y);
            }
            c0 = fmaxf(c0, 0.f); c1 = fmaxf(c1, 0.f);
            c2 = fmaxf(c2, 0.f); c3 = fmaxf(c3, 0.f);
            if (r0 == cEgo) { c0 = s.sEgo[cA]; c1 = s.sEgo[cA + 1]; }
            if (r1 == cEgo) { c2 = s.sEgo[cA]; c3 = s.sEgo[cA + 1]; }
            *reinterpret_cast<__half2*>(&s.Ah1[r0 * AROW + cA]) =
                __floats2half2_rn(c0, c1);
            *reinterpret_cast<__half2*>(&s.Ah1[r1 * AROW + cA]) =
                __floats2half2_rn(c2, c3);
        }
    }
    // q = Wq^T sEgo (warps 0-1 tail work)
    if (tid < 64) {
        const int d = tid;
        float a0 = 0.f, a1 = 0.f;
        #pragma unroll 8
        for (int kp = 0; kp < 32; kp++) {
            float2 wv = __half22float2(__ldg(&dWqp[kp * 64 + d]));
            float2 ev = *reinterpret_cast<const float2*>(&s.sEgo[2 * kp]);
            a0 += ev.x * wv.x;
            a1 += ev.y * wv.y;
        }
        s.sQ[d] = a0 + a1;
    }
    __syncthreads();

    // ---- PH5..PH7: K GEMM -> scores -> softmax -> V GEMM -> P.V ----
    if (npass == 1) {
        // fast path: fused K+V MMAs, V kept in registers across softmax
        const int m_base = mt * 16;
        const int r0 = m_base + (lane >> 2), r1 = r0 + 8;
        u32 A[4][4];
        u32 ab = s2u(s.Ah1 + (m_base + (lane & 15)) * AROW + ((lane >> 4) << 3));
        #pragma unroll
        for (int kt = 0; kt < 4; kt++) ldsm4(A[kt], ab + kt * 32);
        float vV[2][4];
        float p0 = 0.f, p1 = 0.f;
        #pragma unroll
        for (int nt2 = 0; nt2 < 2; nt2++) {
            const int nt = g * 2 + nt2;
            const int cA = nt * 8 + col0;
            float k0 = 0.f, k1 = 0.f, k2 = 0.f, k3 = 0.f;
            float v0 = 0.f, v1 = 0.f, v2 = 0.f, v3 = 0.f;
            #pragma unroll
            for (int kt = 0; kt < 4; kt++) {
                uint2 bk = __ldg(&dFk[(kt * 8 + nt) * 32 + lane]);
                uint2 bv = __ldg(&dFv[(kt * 8 + nt) * 32 + lane]);
                mma16816(k0, k1, k2, k3, A[kt], bk.x, bk.y);
                mma16816(v0, v1, v2, v3, A[kt], bv.x, bv.y);
            }
            float q0 = s.sQ[cA], q1 = s.sQ[cA + 1];
            p0 += k0 * q0 + k1 * q1;
            p1 += k2 * q0 + k3 * q1;
            vV[nt2][0] = v0; vV[nt2][1] = v1; vV[nt2][2] = v2; vV[nt2][3] = v3;
        }
        p0 += __shfl_xor_sync(FULLMASK, p0, 1);
        p1 += __shfl_xor_sync(FULLMASK, p1, 1);
        p0 += __shfl_xor_sync(FULLMASK, p0, 2);
        p1 += __shfl_xor_sync(FULLMASK, p1, 2);
        if ((lane & 3) == 0) {
            bool a0 = uniformF ? (r0 < nTot)
                               : ((r0 < nOth) || (r0 == cEgo && egoAct));
            bool a1 = uniformF ? (r1 < nTot)
                               : ((r1 < nOth) || (r1 == cEgo && egoAct));
            s.sS[g * 64 + r0] = a0 ? p0 * 0.25f : -1e30f;
            s.sS[g * 64 + r1] = a1 ? p1 * 0.25f : -1e30f;
        }
        __syncthreads();
        softmax_phase(s, uniformF, tid);
        __syncthreads();
        const float pr0 = s.sP[g * 64 + r0];
        const float pr1 = s.sP[g * 64 + r1];
        #pragma unroll
        for (int nt2 = 0; nt2 < 2; nt2++) {
            const int cA = (g * 2 + nt2) * 8 + col0;
            float o0 = vV[nt2][0] * pr0 + vV[nt2][2] * pr1;
            float o1 = vV[nt2][1] * pr0 + vV[nt2][3] * pr1;
            #pragma unroll
            for (int off = 4; off < 32; off <<= 1) {
                o0 += __shfl_xor_sync(FULLMASK, o0, off);
                o1 += __shfl_xor_sync(FULLMASK, o1, off);
            }
            if (lane < 4) {
                atomicAdd(&s.sO[cA], o0);
                atomicAdd(&s.sO[cA + 1], o1);
            }
        }
        __syncthreads();
    } else {
        // slow path (nTot > 32, rare): K both passes, softmax, V both passes
        for (int mp = 0; mp < 2; mp++) {
            const int m_base = mp * 32 + mt * 16;
            const int r0 = m_base + (lane >> 2), r1 = r0 + 8;
            u32 A[4][4];
            u32 ab = s2u(s.Ah1 + (m_base + (lane & 15)) * AROW + ((lane >> 4) << 3));
            #pragma unroll
            for (int kt = 0; kt < 4; kt++) ldsm4(A[kt], ab + kt * 32);
            float p0 = 0.f, p1 = 0.f;
            #pragma unroll
            for (int nt2 = 0; nt2 < 2; nt2++) {
                const int nt = g * 2 + nt2;
                const int cA = nt * 8 + col0;
                float k0 = 0.f, k1 = 0.f, k2 = 0.f, k3 = 0.f;
                #pragma unroll
                for (int kt = 0; kt < 4; kt++) {
                    uint2 bk = __ldg(&dFk[(kt * 8 + nt) * 32 + lane]);
                    mma16816(k0, k1, k2, k3, A[kt], bk.x, bk.y);
                }
                float q0 = s.sQ[cA], q1 = s.sQ[cA + 1];
                p0 += k0 * q0 + k1 * q1;
                p1 += k2 * q0 + k3 * q1;
            }
            p0 += __shfl_xor_sync(FULLMASK, p0, 1);
            p1 += __shfl_xor_sync(FULLMASK, p1, 1);
            p0 += __shfl_xor_sync(FULLMASK, p0, 2);
            p1 += __shfl_xor_sync(FULLMASK, p1, 2);
            if ((lane & 3) == 0) {
                bool a0 = uniformF ? (r0 < nTot)
                                   : ((r0 < nOth) || (r0 == cEgo && egoAct));
                bool a1 = uniformF ? (r1 < nTot)
                                   : ((r1 < nOth) || (r1 == cEgo && egoAct));
                s.sS[g * 64 + r0] = a0 ? p0 * 0.25f : -1e30f;
                s.sS[g * 64 + r1] = a1 ? p1 * 0.25f : -1e30f;
            }
        }
        __syncthreads();
        softmax_phase(s, uniformF, tid);
        __syncthreads();
        for (int mp = 0; mp < 2; mp++) {
            const int m_base = mp * 32 + mt * 16;
            const int r0 = m_base + (lane >> 2), r1 = r0 + 8;
            u32 A[4][4];
            u32 ab = s2u(s.Ah1 + (m_base + (lane & 15)) * AROW + ((lane >> 4) << 3));
            #pragma unroll
            for (int kt = 0; kt < 4; kt++) ldsm4(A[kt], ab + kt * 32);
            const float pr0 = s.sP[g * 64 + r0];
            const float pr1 = s.sP[g * 64 + r1];
            #pragma unroll
            for (int nt2 = 0; nt2 < 2; nt2++) {
                const int nt = g * 2 + nt2;
                const int cA = nt * 8 + col0;
                float v0 = 0.f, v1 = 0.f, v2 = 0.f, v3 = 0.f;
                #pragma unroll
                for (int kt = 0; kt < 4; kt++) {
                    uint2 bv = __ldg(&dFv[(kt * 8 + nt) * 32 + lane]);
                    mma16816(v0, v1, v2, v3, A[kt], bv.x, bv.y);
                }
                float o0 = v0 * pr0 + v2 * pr1;
                float o1 = v1 * pr0 + v3 * pr1;
                #pragma unroll
                for (int off = 4; off < 32; off <<= 1) {
                    o0 += __shfl_xor_sync(FULLMASK, o0, off);
                    o1 += __shfl_xor_sync(FULLMASK, o1, off);
                }
                if (lane < 4) {
                    atomicAdd(&s.sO[cA], o0);
                    atomicAdd(&s.sO[cA + 1], o1);
                }
            }
        }
        __syncthreads();
    }

    // ---- PH8: epilogue (out @ Wc + ego) * 0.5 ----
    if (tid < 64) {
        const int d = tid;
        float a0 = 0.f, a1 = 0.f;
        #pragma unroll 8
        for (int kp = 0; kp < 32; kp++) {
            float2 wv = __half22float2(__ldg(&dWcp[kp * 64 + d]));
            float2 ov = *reinterpret_cast<const float2*>(&s.sO[2 * kp]);
            a0 += ov.x * wv.x;
            a1 += ov.y * wv.y;
        }
        out[b * 64 + d] = ((a0 + a1) + s.sEgo[d]) * 0.5f;
    }
}

extern "C" void kernel_launch(void* const* d_in, const int* in_sizes, int n_in,
                              void* d_out, int out_size) {
    (void)in_sizes; (void)n_in; (void)out_size;
    const float* x      = (const float*)d_in[0];
    const float* ego_w0 = (const float*)d_in[1];
    const float* ego_b0 = (const float*)d_in[2];
    const float* ego_w1 = (const float*)d_in[3];
    const float* ego_b1 = (const float*)d_in[4];
    const float* oth_w0 = (const float*)d_in[5];
    const float* oth_b0 = (const float*)d_in[6];
    const float* oth_w1 = (const float*)d_in[7];
    const float* oth_b1 = (const float*)d_in[8];
    const float* Wk     = (const float*)d_in[9];
    const float* Wv     = (const float*)d_in[10];
    const float* Wq     = (const float*)d_in[11];
    const float* Wc     = (const float*)d_in[12];
    float* out = (float*)d_out;

    prep_weights<<<8, 256>>>(oth_w0, oth_w1, Wk, Wv, ego_w1, Wq, Wc);
    ego_attn_kernel<<<8192, NTHR>>>(x, ego_w0, ego_b0, ego_b1,
                                    oth_b0, oth_b1, out);
}